// round 15
// baseline (speedup 1.0000x reference)
#include <cuda_runtime.h>

#define SB 2048
#define TB 64
#define NB 256
#define NBLK 128     // 2 chains per block, 2 warps per chain -> 1 warp per SMSP
#define PF 8         // emission prefetch depth (steps)

typedef unsigned long long ull;

__device__ float g_part[NB];
__device__ unsigned int g_cnt;   // zero-init; reset by last block each run

static __device__ __forceinline__ ull pk2(float a, float b) {
    ull r; asm("mov.b64 %0,{%1,%2};" : "=l"(r) : "f"(a), "f"(b)); return r;
}
static __device__ __forceinline__ void upk2(ull v, float& a, float& b) {
    asm("mov.b64 {%0,%1},%2;" : "=f"(a), "=f"(b) : "l"(v));
}
static __device__ __forceinline__ ull fma2(ull a, ull b, ull c) {
    ull d; asm("fma.rn.f32x2 %0,%1,%2,%3;" : "=l"(d) : "l"(a), "l"(b), "l"(c)); return d;
}
static __device__ __forceinline__ ull add2(ull a, ull b) {
    ull d; asm("add.rn.f32x2 %0,%1,%2;" : "=l"(d) : "l"(a), "l"(b)); return d;
}
static __device__ __forceinline__ void barx(int id) {
    asm volatile("bar.sync %0, 64;" :: "r"(id) : "memory");
}

__global__ __launch_bounds__(128, 1) void crf_main_kernel(
    const float* __restrict__ emis,     // (B, S, T)
    const float* __restrict__ startT,   // (T)
    const float* __restrict__ endT,     // (T)
    const float* __restrict__ trans,    // (T, T)
    const int*   __restrict__ tags,     // (B, S)
    const int*   __restrict__ maskp,    // (B, S)
    float*       __restrict__ out)
{
    const int tid  = threadIdx.x;
    const int w    = tid >> 5;
    const int lane = tid & 31;
    const int c    = w >> 1;                // chain in block: warps {2c, 2c+1}
    const int jh   = w & 1;                 // state-vector half
    const int j    = (jh << 5) | lane;      // owned state 0..63
    const int b    = blockIdx.x * 2 + c;
    const int barid = c + 1;

    const float* __restrict__ em = emis + (size_t)b * SB * TB;
    const int*   __restrict__ tg = tags  + b * SB;
    const int*   __restrict__ mk = maskp + b * SB;

    __shared__ __align__(16) float p[2][2][TB];  // [chain][parity][state]
    __shared__ float nred[2][2];                 // numerator partial per (chain, warp)
    __shared__ int   mred[2][2];
    __shared__ float red[2][2];
    __shared__ float sred[4];
    __shared__ int   lastflag;

    // ---------------- numerator: gold tag path (64-way parallel per chain) ----------
    float nacc = 0.f;
    int   macc = 0;
    for (int t = j; t < SB; t += TB) {
        int m = mk[t];
        macc += m;
        if (t > 0 && m) {
            int tp = tg[t - 1], tc = tg[t];
            nacc += trans[tp * TB + tc] + em[t * TB + tc];
        }
    }
    if (j == 0) nacc += startT[tg[0]] + em[tg[0]];
    #pragma unroll
    for (int o = 16; o; o >>= 1) {
        nacc += __shfl_down_sync(0xffffffffu, nacc, o);
        macc += __shfl_down_sync(0xffffffffu, macc, o);
    }
    if (lane == 0) { nred[c][jh] = nacc; mred[c][jh] = macc; }

    // ---------------- E = exp(transitions) column j into registers -----------------
    ull Ecol[TB / 2];
    #pragma unroll
    for (int i = 0; i < TB / 2; i++) {
        float e0 = expf(trans[(2 * i) * TB + j]);
        float e1 = expf(trans[(2 * i + 1) * TB + j]);
        Ecol[i] = pk2(e0, e1);
    }

    // ---------------- init: p = exp(start + em0) -----------------------------------
    float pq = __expf(startT[j] + em[j]);
    p[c][0][j] = pq;

    // prefetch ring, distance PF: RAW emissions (exp applied at use time)
    float emr[PF];
    int   mkr[PF];
    #pragma unroll
    for (int k = 0; k < PF; k++) {
        int t = 1 + k;
        emr[k] = em[t * TB + j];
        mkr[k] = mk[t];
    }

    int Eacc = 0;   // exact log2 offset (power-of-two renormalization)

    // ---------------- forward recursion ---------------------------------------------
    #pragma unroll 1
    for (int tb = 1; tb < SB; tb += PF) {
        #pragma unroll
        for (int k = 0; k < PF; k++) {
            const int t = tb + k;
            const int rb = k & 1;        // read parity ((t-1)&1; tb odd)
            const int wb = rb ^ 1;

            barx(barid);

            float eem = __expf(emr[k]);  // loaded PF steps ago — no LDG stall

            const ulonglong2* __restrict__ pv = (const ulonglong2*)p[c][rb];

            // first vector of p; low float is p_0 -> exact power-of-2 normalizer
            ulonglong2 v0 = pv[0];
            unsigned int u0 = (unsigned int)v0.x;       // bits of p_0
            int eb = (int)((u0 >> 23) & 0xff);
            float scale = __int_as_float((254 - eb) << 23);   // 2^(127-eb), exact
            float f = eem * scale;

            // dot: s_j = sum_i p[i] * E[i][j]  (16x broadcast LDS.128, 32x FFMA2)
            ull a0 = fma2(v0.x, Ecol[0], 0ull);
            ull a1 = fma2(v0.y, Ecol[1], 0ull);
            ull a2 = 0ull, a3 = 0ull;
            #pragma unroll
            for (int i = 1; i < 13; i += 4) {
                ulonglong2 w0 = pv[i + 0];
                a2 = fma2(w0.x, Ecol[2 * i + 0], a2);
                a3 = fma2(w0.y, Ecol[2 * i + 1], a3);
                ulonglong2 w1 = pv[i + 1];
                a0 = fma2(w1.x, Ecol[2 * i + 2], a0);
                a1 = fma2(w1.y, Ecol[2 * i + 3], a1);
                ulonglong2 w2 = pv[i + 2];
                a2 = fma2(w2.x, Ecol[2 * i + 4], a2);
                a3 = fma2(w2.y, Ecol[2 * i + 5], a3);
                ulonglong2 w3 = pv[i + 3];
                a0 = fma2(w3.x, Ecol[2 * i + 6], a0);
                a1 = fma2(w3.y, Ecol[2 * i + 7], a1);
            }
            {   // tail: pv[13..15], Ecol[26..31]
                ulonglong2 w0 = pv[13];
                a2 = fma2(w0.x, Ecol[26], a2);
                a3 = fma2(w0.y, Ecol[27], a3);
                ulonglong2 w1 = pv[14];
                a0 = fma2(w1.x, Ecol[28], a0);
                a1 = fma2(w1.y, Ecol[29], a1);
                ulonglong2 w2 = pv[15];
                a2 = fma2(w2.x, Ecol[30], a2);
                a3 = fma2(w2.y, Ecol[31], a3);
            }
            ull sa = add2(add2(a0, a1), add2(a2, a3));
            float s0, s1; upk2(sa, s0, s1);
            float s = s0 + s1;

            // alpha' = M + (eb-127)*ln2 + log(s * eem)   [exact renormalization]
            float q = mkr[k] ? s * f : pq;
            pq = q;
            p[c][wb][j] = q;
            Eacc += mkr[k] ? (eb - 127) : 0;

            // prefetch t+PF (raw load only)
            if (t + PF < SB) {
                emr[k] = em[(t + PF) * TB + j];
                mkr[k] = mk[t + PF];
            }
        }
    }

    // ---------------- finish: den = M + log(sum_j p_j * exp(endT_j)) ---------------
    float term = pq * __expf(endT[j]);       // final alpha lives in pq
    #pragma unroll
    for (int o = 16; o; o >>= 1)
        term += __shfl_down_sync(0xffffffffu, term, o);
    if (lane == 0) red[c][jh] = term;
    barx(barid);

    if (j == 0) {
        double Mtot = (double)Eacc * 0.6931471805599453;
        float total = red[c][0] + red[c][1];
        float den = (float)(Mtot + (double)logf(total));
        float num = nred[c][0] + nred[c][1];
        int   se  = mred[c][0] + mred[c][1] - 1;
        num += endT[tg[se]];
        g_part[b] = den - num;
    }

    // ---------------- fused grid reduction: last block computes the mean -----------
    __syncthreads();
    if (tid == 0) {
        __threadfence();
        unsigned int old = atomicAdd(&g_cnt, 1u);
        lastflag = (old == NBLK - 1);
    }
    __syncthreads();
    if (lastflag) {
        __threadfence();
        float v = g_part[tid] + g_part[tid + 128];
        #pragma unroll
        for (int o = 16; o; o >>= 1)
            v += __shfl_down_sync(0xffffffffu, v, o);
        if (lane == 0) sred[w] = v;
        __syncthreads();
        if (tid == 0) {
            float ssum = sred[0] + sred[1] + sred[2] + sred[3];
            out[0] = ssum / (float)NB;   // mean(den - num)
            g_cnt = 0;                    // reset for next replay
        }
    }
}

extern "C" void kernel_launch(void* const* d_in, const int* in_sizes, int n_in,
                              void* d_out, int out_size) {
    const float* emissions = (const float*)d_in[0];
    const float* startT    = (const float*)d_in[1];
    const float* endT      = (const float*)d_in[2];
    const float* trans     = (const float*)d_in[3];
    const int*   tags      = (const int*)d_in[4];
    const int*   mask      = (const int*)d_in[5];
    (void)in_sizes; (void)n_in; (void)out_size;

    crf_main_kernel<<<NBLK, 128>>>(emissions, startT, endT, trans, tags, mask,
                                   (float*)d_out);
}

// round 16
// speedup vs baseline: 1.5130x; 1.5130x over previous
#include <cuda_runtime.h>

#define SB 2048
#define TB 64
#define NB 256
#define NBLK 128     // 2 chains per block, 2 warps per chain -> 1 warp per SMSP
#define PF 8         // emission prefetch depth (steps)

typedef unsigned long long ull;

__device__ float g_part[NB];
__device__ unsigned int g_cnt;   // zero-init; reset by last block each run

static __device__ __forceinline__ ull pk2(float a, float b) {
    ull r; asm("mov.b64 %0,{%1,%2};" : "=l"(r) : "f"(a), "f"(b)); return r;
}
static __device__ __forceinline__ void upk2(ull v, float& a, float& b) {
    asm("mov.b64 {%0,%1},%2;" : "=f"(a), "=f"(b) : "l"(v));
}
static __device__ __forceinline__ ull fma2(ull a, ull b, ull c) {
    ull d; asm("fma.rn.f32x2 %0,%1,%2,%3;" : "=l"(d) : "l"(a), "l"(b), "l"(c)); return d;
}
static __device__ __forceinline__ ull add2(ull a, ull b) {
    ull d; asm("add.rn.f32x2 %0,%1,%2;" : "=l"(d) : "l"(a), "l"(b)); return d;
}
static __device__ __forceinline__ void barx(int id) {
    asm volatile("bar.sync %0, 64;" :: "r"(id) : "memory");
}

__global__ __launch_bounds__(128, 1) void crf_main_kernel(
    const float* __restrict__ emis,     // (B, S, T)
    const float* __restrict__ startT,   // (T)
    const float* __restrict__ endT,     // (T)
    const float* __restrict__ trans,    // (T, T)
    const int*   __restrict__ tags,     // (B, S)
    const int*   __restrict__ maskp,    // (B, S)
    float*       __restrict__ out)
{
    const int tid  = threadIdx.x;
    const int w    = tid >> 5;
    const int lane = tid & 31;
    const int c    = w >> 1;                // chain in block: warps {2c, 2c+1}
    const int jh   = w & 1;                 // state-vector half
    const int j    = (jh << 5) | lane;      // owned state 0..63
    const int b    = blockIdx.x * 2 + c;
    const int barid = c + 1;

    const float* __restrict__ em = emis + (size_t)b * SB * TB;
    const int*   __restrict__ tg = tags  + b * SB;
    const int*   __restrict__ mk = maskp + b * SB;

    __shared__ __align__(16) float p[2][2][TB];  // [chain][parity][state]
    __shared__ float craw[2][2];                 // [chain][parity] raw s_0 (normalizer seed)
    __shared__ float nred[2][2];                 // numerator partial per (chain, warp)
    __shared__ int   mred[2][2];
    __shared__ float red[2][2];
    __shared__ float sred[4];
    __shared__ int   lastflag;

    // ---------------- numerator: gold tag path (64-way parallel per chain) ----------
    float nacc = 0.f;
    int   macc = 0;
    for (int t = j; t < SB; t += TB) {
        int m = mk[t];
        macc += m;
        if (t > 0 && m) {
            int tp = tg[t - 1], tc = tg[t];
            nacc += trans[tp * TB + tc] + em[t * TB + tc];
        }
    }
    if (j == 0) nacc += startT[tg[0]] + em[tg[0]];
    #pragma unroll
    for (int o = 16; o; o >>= 1) {
        nacc += __shfl_down_sync(0xffffffffu, nacc, o);
        macc += __shfl_down_sync(0xffffffffu, macc, o);
    }
    if (lane == 0) { nred[c][jh] = nacc; mred[c][jh] = macc; }

    // ---------------- E = exp(transitions) column j into registers -----------------
    ull Ecol[TB / 2];
    #pragma unroll
    for (int i = 0; i < TB / 2; i++) {
        float e0 = expf(trans[(2 * i) * TB + j]);
        float e1 = expf(trans[(2 * i + 1) * TB + j]);
        Ecol[i] = pk2(e0, e1);
    }

    // ---------------- init: p = exp(start + em0) -----------------------------------
    float pq = __expf(startT[j] + em[j]);
    p[c][0][j] = pq;
    if (j == 0) craw[c][0] = 1.0f;

    // prefetch ring, distance PF: RAW emissions (exp applied at use time)
    float emr[PF];
    int   mkr[PF];
    #pragma unroll
    for (int k = 0; k < PF; k++) {
        int t = 1 + k;
        emr[k] = em[t * TB + j];
        mkr[k] = mk[t];
    }

    int Eacc = 0;   // exact log2 offset (power-of-two renormalization)

    // ---------------- one forward step (macro-like lambda, fully inlined) ----------
    auto step = [&](int t, int k) {
        const int rb = k & 1;        // read parity ((t-1)&1; t = tb + k, tb odd, tb%8==1)
        const int wb = rb ^ 1;

        barx(barid);

        // normalizer path — exact power-of-two, ALU only, hidden under the dot
        float eem = __expf(emr[k]);                 // loaded PF steps ago — no LDG stall
        float cr  = craw[c][rb];
        int   eb  = (__float_as_int(cr) >> 23) & 0xff;
        float scale = __int_as_float((254 - eb) << 23);   // 2^(127-eb), exact
        float f = eem * scale;                       // exact mul by pow2

        // dot: s_j = sum_i p[i] * E[i][j]  (16x broadcast LDS.128, 32x FFMA2)
        const ulonglong2* __restrict__ pv = (const ulonglong2*)p[c][rb];
        ull a0 = 0ull, a1 = 0ull, a2 = 0ull, a3 = 0ull;
        #pragma unroll
        for (int i = 0; i < 16; i += 4) {
            ulonglong2 v0 = pv[i + 0];
            a0 = fma2(v0.x, Ecol[2 * i + 0], a0);
            a1 = fma2(v0.y, Ecol[2 * i + 1], a1);
            ulonglong2 v1 = pv[i + 1];
            a2 = fma2(v1.x, Ecol[2 * i + 2], a2);
            a3 = fma2(v1.y, Ecol[2 * i + 3], a3);
            ulonglong2 v2 = pv[i + 2];
            a0 = fma2(v2.x, Ecol[2 * i + 4], a0);
            a1 = fma2(v2.y, Ecol[2 * i + 5], a1);
            ulonglong2 v3 = pv[i + 3];
            a2 = fma2(v3.x, Ecol[2 * i + 6], a2);
            a3 = fma2(v3.y, Ecol[2 * i + 7], a3);
        }
        ull sa = add2(add2(a0, a1), add2(a2, a3));
        float s0, s1; upk2(sa, s0, s1);
        float s = s0 + s1;

        // alpha' = Eacc*ln2 + log p ; division by 2^(eb-127) matched by Eacc add
        float q = mkr[k] ? s * f : pq;
        pq = q;
        p[c][wb][j] = q;
        if (j == 0) craw[c][wb] = s;                 // next step's normalizer seed
        Eacc += mkr[k] ? (eb - 127) : 0;

        // prefetch t+PF (raw load only — no dependent math)
        if (t + PF < SB) {
            emr[k] = em[(t + PF) * TB + j];
            mkr[k] = mk[t + PF];
        }
    };

    // ---------------- forward recursion: t = 1 .. 2047, no phantom step ------------
    // full 8-step blocks: tb = 1, 9, ..., 2033  -> t = 1 .. 2040
    #pragma unroll 1
    for (int tb = 1; tb + PF <= SB; tb += PF) {
        #pragma unroll
        for (int k = 0; k < PF; k++)
            step(tb + k, k);
    }
    // epilogue: t = 2041 .. 2047 (7 steps), same ring slots k = 0..6
    {
        const int tb = ((SB - 1 - PF) / PF) * PF + 1 + PF;   // 2041
        #pragma unroll
        for (int k = 0; k < PF - 1; k++)
            step(tb + k, k);
    }

    // ---------------- finish: den = Eacc*ln2 + log(sum_j p_j * exp(endT_j)) --------
    float term = pq * __expf(endT[j]);       // final alpha lives in pq
    #pragma unroll
    for (int o = 16; o; o >>= 1)
        term += __shfl_down_sync(0xffffffffu, term, o);
    if (lane == 0) red[c][jh] = term;
    barx(barid);

    if (j == 0) {
        double Mtot = (double)Eacc * 0.6931471805599453;
        float total = red[c][0] + red[c][1];
        float den = (float)(Mtot + (double)logf(total));
        float num = nred[c][0] + nred[c][1];
        int   se  = mred[c][0] + mred[c][1] - 1;
        num += endT[tg[se]];
        g_part[b] = den - num;
    }

    // ---------------- fused grid reduction: last block computes the mean -----------
    __syncthreads();
    if (tid == 0) {
        __threadfence();
        unsigned int old = atomicAdd(&g_cnt, 1u);
        lastflag = (old == NBLK - 1);
    }
    __syncthreads();
    if (lastflag) {
        __threadfence();
        float v = g_part[tid] + g_part[tid + 128];
        #pragma unroll
        for (int o = 16; o; o >>= 1)
            v += __shfl_down_sync(0xffffffffu, v, o);
        if (lane == 0) sred[w] = v;
        __syncthreads();
        if (tid == 0) {
            float ssum = sred[0] + sred[1] + sred[2] + sred[3];
            out[0] = ssum / (float)NB;   // mean(den - num)
            g_cnt = 0;                    // reset for next replay
        }
    }
}

extern "C" void kernel_launch(void* const* d_in, const int* in_sizes, int n_in,
                              void* d_out, int out_size) {
    const float* emissions = (const float*)d_in[0];
    const float* startT    = (const float*)d_in[1];
    const float* endT      = (const float*)d_in[2];
    const float* trans     = (const float*)d_in[3];
    const int*   tags      = (const int*)d_in[4];
    const int*   mask      = (const int*)d_in[5];
    (void)in_sizes; (void)n_in; (void)out_size;

    crf_main_kernel<<<NBLK, 128>>>(emissions, startT, endT, trans, tags, mask,
                                   (float*)d_out);
}